// round 8
// baseline (speedup 1.0000x reference)
#include <cuda_runtime.h>
#include <cuda_bf16.h>
#include <cstdint>

#define BB 32
#define SS 256
#define HH 768
#define NH 12
#define HD 64
#define BH (BB*NH)          // 384

// Scratch (device globals; no runtime allocation)
__device__ float g_wt[(size_t)3*HH*HH];            // W transposed [nw][n][k], tf32
// QKV outputs as bf16 hi/lo, layout [bh][s][d]
__device__ unsigned short g_qh[(size_t)BH*SS*HD];
__device__ unsigned short g_ql[(size_t)BH*SS*HD];
__device__ unsigned short g_kh[(size_t)BH*SS*HD];
__device__ unsigned short g_kl[(size_t)BH*SS*HD];
__device__ unsigned short g_vh[(size_t)BH*SS*HD];
__device__ unsigned short g_vl[(size_t)BH*SS*HD];

// ---------------------------------------------------------------------------
// PTX helpers (sm_80-era; legal on plain sm_100 target)
// ---------------------------------------------------------------------------
__device__ __forceinline__ uint32_t smem_to_u32(const void* p) {
    uint32_t a;
    asm("{ .reg .u64 t; cvta.to.shared.u64 t, %1; cvt.u32.u64 %0, t; }" : "=r"(a) : "l"(p));
    return a;
}
__device__ __forceinline__ void cp16(uint32_t dst, const void* src) {
    asm volatile("cp.async.cg.shared.global [%0], [%1], 16;" :: "r"(dst), "l"(src));
}
#define CP_COMMIT() asm volatile("cp.async.commit_group;" ::: "memory")
#define CP_WAIT(n)  asm volatile("cp.async.wait_group %0;" :: "n"(n) : "memory")
__device__ __forceinline__ void ldm_x4(uint32_t* r, uint32_t addr) {
    asm volatile("ldmatrix.sync.aligned.m8n8.x4.shared.b16 {%0,%1,%2,%3}, [%4];"
        : "=r"(r[0]), "=r"(r[1]), "=r"(r[2]), "=r"(r[3]) : "r"(addr));
}
__device__ __forceinline__ void ldm_x4_t(uint32_t* r, uint32_t addr) {
    asm volatile("ldmatrix.sync.aligned.m8n8.x4.trans.shared.b16 {%0,%1,%2,%3}, [%4];"
        : "=r"(r[0]), "=r"(r[1]), "=r"(r[2]), "=r"(r[3]) : "r"(addr));
}
__device__ __forceinline__ void mma16816(float* c, const uint32_t* a, const uint32_t* b) {
    asm volatile("mma.sync.aligned.m16n8k16.row.col.f32.bf16.bf16.f32 "
        "{%0,%1,%2,%3}, {%4,%5,%6,%7}, {%8,%9}, {%0,%1,%2,%3};"
        : "+f"(c[0]), "+f"(c[1]), "+f"(c[2]), "+f"(c[3])
        : "r"(a[0]), "r"(a[1]), "r"(a[2]), "r"(a[3]), "r"(b[0]), "r"(b[1]));
}
__device__ __forceinline__ void mma_tf32(float* c, const uint32_t* a, uint32_t b0, uint32_t b1) {
    asm volatile("mma.sync.aligned.m16n8k8.row.col.f32.tf32.tf32.f32 "
        "{%0,%1,%2,%3}, {%4,%5,%6,%7}, {%8,%9}, {%0,%1,%2,%3};"
        : "+f"(c[0]), "+f"(c[1]), "+f"(c[2]), "+f"(c[3])
        : "r"(a[0]), "r"(a[1]), "r"(a[2]), "r"(a[3]), "r"(b0), "r"(b1));
}
__device__ __forceinline__ float to_tf32(float x) {
    uint32_t u = __float_as_uint(x), o;
    asm("cvt.rna.tf32.f32 %0, %1;" : "=r"(o) : "r"(u));
    return __uint_as_float(o);
}
__device__ __forceinline__ uint32_t cvt_rna_u32(uint32_t u) {
    uint32_t o;
    asm("cvt.rna.tf32.f32 %0, %1;" : "=r"(o) : "r"(u));
    return o;
}
__device__ __forceinline__ void split2(float x0, float x1, uint32_t& h, uint32_t& l) {
    __nv_bfloat16 h0 = __float2bfloat16(x0), h1 = __float2bfloat16(x1);
    __nv_bfloat16 l0 = __float2bfloat16(x0 - __bfloat162float(h0));
    __nv_bfloat16 l1 = __float2bfloat16(x1 - __bfloat162float(h1));
    h = (uint32_t)__bfloat16_as_ushort(h0) | ((uint32_t)__bfloat16_as_ushort(h1) << 16);
    l = (uint32_t)__bfloat16_as_ushort(l0) | ((uint32_t)__bfloat16_as_ushort(l1) << 16);
}

// ---------------------------------------------------------------------------
// Prep: W -> transposed tf32 (coalesced tile transpose)
// ---------------------------------------------------------------------------
__global__ __launch_bounds__(256) void prep_w(
    const float* __restrict__ Wq, const float* __restrict__ Wk, const float* __restrict__ Wv)
{
    __shared__ float tile[32][33];
    const int nw = blockIdx.z;
    const float* W = (nw == 0) ? Wq : (nw == 1) ? Wk : Wv;
    const int k0 = blockIdx.x * 32;
    const int n0 = blockIdx.y * 32;
    const int tx = threadIdx.x & 31;
    const int ty = threadIdx.x >> 5;          // 0..7
    #pragma unroll
    for (int s = 0; s < 32; s += 8)
        tile[ty + s][tx] = W[(size_t)(k0 + ty + s) * HH + n0 + tx];
    __syncthreads();
    #pragma unroll
    for (int s = 0; s < 32; s += 8)
        g_wt[((size_t)nw * HH + n0 + ty + s) * HH + k0 + tx] = to_tf32(tile[tx][ty + s]);
}

// ---------------------------------------------------------------------------
// QKV GEMM via mma.sync tf32, 3-stage cp.async ring (prefetch distance 2),
// ONE barrier per chunk, placed AFTER the per-thread wait (visibility-safe):
//   CP_WAIT -> __syncthreads -> stage(c+2) -> compute(c)
// ---------------------------------------------------------------------------
#define PITCH_F 36                      // floats per smem row (144 B)
#define QST_B  18432                    // B tile offset within stage
#define QST_STRIDE 36864                // bytes per stage
#define QKV_SMEM (3 * QST_STRIDE)       // 110592

__global__ __launch_bounds__(256, 2) void qkv_mma(
    const float* __restrict__ X,
    const float* __restrict__ bq, const float* __restrict__ bk, const float* __restrict__ bv)
{
    extern __shared__ __align__(16) char qsm[];
    const uint32_t sb = smem_to_u32(qsm);

    const int tid  = threadIdx.x;
    const int wid  = tid >> 5;
    const int lane = tid & 31;

    const int m0 = blockIdx.x * 128;
    const int nw = blockIdx.y / 6;
    const int n0 = (blockIdx.y % 6) * 128;

    const float* bias = (nw == 0) ? bq : (nw == 1) ? bk : bv;
    unsigned short* dsth = (nw == 0) ? g_qh : (nw == 1) ? g_kh : g_vh;
    unsigned short* dstl = (nw == 0) ? g_ql : (nw == 1) ? g_kl : g_vl;

    const int wm = (wid >> 2) * 64;
    const int wn = (wid & 3) * 32;

    // ldmatrix lane addressing (tf32-as-b16 overlay): row + 16B column select
    const int ar = (lane & 7) + ((lane >> 3) & 1) * 8;
    const uint32_t asel = (lane >> 4) * 16;
    const uint32_t a_off = (uint32_t)(wm + ar) * (PITCH_F * 4) + asel;
    const uint32_t b_off = (uint32_t)(wn + ar) * (PITCH_F * 4) + asel;

    float acc[4][4][4];
    #pragma unroll
    for (int i = 0; i < 4; i++)
        #pragma unroll
        for (int j = 0; j < 4; j++)
            #pragma unroll
            for (int c = 0; c < 4; c++) acc[i][j][c] = 0.f;

    #define QKV_STAGE(c_, s_)                                                        \
    do {                                                                             \
        const int k0_ = (c_) * 32;                                                   \
        const uint32_t stb_ = sb + (s_) * QST_STRIDE;                                \
        _Pragma("unroll")                                                            \
        for (int i_ = 0; i_ < 4; i_++) {                                             \
            const int idx_ = tid + i_ * 256;      /* 0..1023 */                      \
            const int r_  = idx_ >> 3;                                               \
            const int sg_ = idx_ & 7;                                                \
            const size_t ga_ = (size_t)(m0 + r_) * HH + k0_ + sg_ * 4;               \
            const size_t gb_ = ((size_t)nw * HH + n0 + r_) * HH + k0_ + sg_ * 4;     \
            const uint32_t so_ = (r_ * PITCH_F + sg_ * 4) * 4;                       \
            cp16(stb_ + so_, X + ga_);                                               \
            cp16(stb_ + QST_B + so_, g_wt + gb_);                                    \
        }                                                                            \
        CP_COMMIT();                                                                 \
    } while (0)

    QKV_STAGE(0, 0);
    QKV_STAGE(1, 1);

    for (int chunk = 0; chunk < 24; chunk++) {
        // Own chunk-c copies done; barrier publishes ALL threads' copies and
        // retires all reads of the buffer stage(c+2) will overwrite.
        if (chunk < 23) CP_WAIT(1); else CP_WAIT(0);
        __syncthreads();
        if (chunk + 2 < 24) QKV_STAGE(chunk + 2, (chunk + 2) % 3);

        const int st = chunk % 3;
        const uint32_t sA = sb + st * QST_STRIDE;
        const uint32_t sB = sA + QST_B;

        #pragma unroll
        for (int j = 0; j < 4; j++) {              // k8 steps within chunk
            const uint32_t kadd = j * 32;          // 8 floats = 32 B
            uint32_t a[16], bb[8];
            #pragma unroll
            for (int mt = 0; mt < 4; mt++)
                ldm_x4(&a[mt * 4], sA + a_off + kadd + mt * (16 * PITCH_F * 4));
            // A staged as raw fp32 -> round to tf32 here (matches cvt.rna prep)
            #pragma unroll
            for (int q = 0; q < 16; q++) a[q] = cvt_rna_u32(a[q]);
            #pragma unroll
            for (int p = 0; p < 2; p++)
                ldm_x4(&bb[p * 4], sB + b_off + kadd + p * (16 * PITCH_F * 4));
            #pragma unroll
            for (int mt = 0; mt < 4; mt++) {
                mma_tf32(acc[mt][0], &a[mt * 4], bb[0], bb[2]);
                mma_tf32(acc[mt][1], &a[mt * 4], bb[1], bb[3]);
                mma_tf32(acc[mt][2], &a[mt * 4], bb[4], bb[6]);
                mma_tf32(acc[mt][3], &a[mt * 4], bb[5], bb[7]);
            }
        }
    }

    // Epilogue: bias + bf16 hi/lo split, scatter to [bh][s][d]
    #pragma unroll
    for (int mt = 0; mt < 4; mt++) {
        #pragma unroll
        for (int nt = 0; nt < 4; nt++) {
            const int n  = n0 + wn + nt * 8 + (lane & 3) * 2;
            const int h  = n >> 6;
            const int d  = n & 63;
            const float b0 = __ldg(&bias[n]);
            const float b1 = __ldg(&bias[n + 1]);
            #pragma unroll
            for (int half = 0; half < 2; half++) {
                const int m  = m0 + wm + mt * 16 + (lane >> 2) + half * 8;
                const int b_ = m >> 8;
                const int s  = m & 255;
                const float x0 = acc[mt][nt][half * 2]     + b0;
                const float x1 = acc[mt][nt][half * 2 + 1] + b1;
                uint32_t hh, ll;
                split2(x0, x1, hh, ll);
                const size_t di = (size_t)((b_ * NH + h) * SS + s) * HD + d;
                *(uint32_t*)&dsth[di] = hh;
                *(uint32_t*)&dstl[di] = ll;
            }
        }
    }
}

// ---------------------------------------------------------------------------
// Fused attention: scores (QK^T, 3-term bf16) -> cm*scale+mask -> softmax -> P@V
// ---------------------------------------------------------------------------
#define P2 72
#define OFF_Q_H  0
#define OFF_Q_L  9216
#define OFF_K_H  18432
#define OFF_K_L  55296
#define OFF_MAX  92160
#define OFF_SUM  92672
#define ATT_SMEM 93184
#define OFF_CTX  0

__global__ __launch_bounds__(256, 2) void att_kernel(
    const float* __restrict__ CM, const float* __restrict__ MSK,
    const float* __restrict__ wcm_p, const float* __restrict__ bcm_p,
    float* __restrict__ out)
{
    extern __shared__ __align__(16) char smem[];
    const uint32_t sb = smem_to_u32(smem);

    const int tid  = threadIdx.x;
    const int wid  = tid >> 5;
    const int lane = tid & 31;
    const int wm = wid >> 1;
    const int wn = wid & 1;

    const int bh = blockIdx.y;
    const int qt = blockIdx.x;
    const int b  = bh / NH;
    const int h  = bh % NH;

    #pragma unroll
    for (int i = 0; i < 2; i++) {
        const int s_ = tid + i * 256;
        const int r = s_ >> 3, sg = s_ & 7;
        const size_t gi = ((size_t)bh * SS + qt * 64 + r) * HD + sg * 8;
        const uint32_t so = (r * P2 + sg * 8) * 2;
        cp16(sb + OFF_Q_H + so, g_qh + gi);
        cp16(sb + OFF_Q_L + so, g_ql + gi);
    }
    #pragma unroll
    for (int i = 0; i < 8; i++) {
        const int s_ = tid + i * 256;
        const int r = s_ >> 3, sg = s_ & 7;
        const size_t gi = ((size_t)bh * SS + r) * HD + sg * 8;
        const uint32_t so = (r * P2 + sg * 8) * 2;
        cp16(sb + OFF_K_H + so, g_kh + gi);
        cp16(sb + OFF_K_L + so, g_kl + gi);
    }
    CP_COMMIT();
    CP_WAIT(0);
    __syncthreads();

    const uint32_t a_off = ((wm * 16 + (lane & 15)) * P2 + (lane >> 4) * 8) * 2;
    const uint32_t b_off = ((wn * 128 + (lane >> 4) * 8 + (lane & 7)) * P2 + ((lane >> 3) & 1) * 8) * 2;

    float acc[16][4];
    #pragma unroll
    for (int nt = 0; nt < 16; nt++)
        #pragma unroll
        for (int c = 0; c < 4; c++) acc[nt][c] = 0.f;

    #pragma unroll
    for (int ks = 0; ks < 4; ks++) {
        const uint32_t kadd = ks * 32;
        uint32_t ah[4], al[4], bb[32];
        ldm_x4(ah, sb + OFF_Q_H + a_off + kadd);
        ldm_x4(al, sb + OFF_Q_L + a_off + kadd);
        #pragma unroll
        for (int g = 0; g < 8; g++)
            ldm_x4(&bb[g * 4], sb + OFF_K_H + b_off + kadd + g * (16 * P2 * 2));
        #pragma unroll
        for (int nt = 0; nt < 16; nt++) mma16816(acc[nt], ah, &bb[nt * 2]);
        #pragma unroll
        for (int nt = 0; nt < 16; nt++) mma16816(acc[nt], al, &bb[nt * 2]);
        #pragma unroll
        for (int g = 0; g < 8; g++)
            ldm_x4(&bb[g * 4], sb + OFF_K_L + b_off + kadd + g * (16 * P2 * 2));
        #pragma unroll
        for (int nt = 0; nt < 16; nt++) mma16816(acc[nt], ah, &bb[nt * 2]);
    }

    const int rl0 = wm * 16 + (lane >> 2);
    const int rl1 = rl0 + 8;
    const int r0g = qt * 64 + rl0;
    const int r1g = qt * 64 + rl1;
    const float wv  = __ldg(wcm_p);
    const float bvv = __ldg(bcm_p);
    const float* CMb = CM + (size_t)b * SS * SS;

    float mx0 = -1e30f, mx1 = -1e30f;
    #pragma unroll
    for (int nt = 0; nt < 16; nt++) {
        const int c = wn * 128 + nt * 8 + (lane & 3) * 2;
        float2 cm0 = *(const float2*)&CMb[(size_t)r0g * SS + c];
        float2 cm1 = *(const float2*)&CMb[(size_t)r1g * SS + c];
        float2 mk  = *(const float2*)&MSK[b * SS + c];
        acc[nt][0] = acc[nt][0] * 0.125f * fmaf(wv, cm0.x, bvv) + mk.x;
        acc[nt][1] = acc[nt][1] * 0.125f * fmaf(wv, cm0.y, bvv) + mk.y;
        acc[nt][2] = acc[nt][2] * 0.125f * fmaf(wv, cm1.x, bvv) + mk.x;
        acc[nt][3] = acc[nt][3] * 0.125f * fmaf(wv, cm1.y, bvv) + mk.y;
        mx0 = fmaxf(mx0, fmaxf(acc[nt][0], acc[nt][1]));
        mx1 = fmaxf(mx1, fmaxf(acc[nt][2], acc[nt][3]));
    }
    mx0 = fmaxf(mx0, __shfl_xor_sync(~0u, mx0, 1));
    mx0 = fmaxf(mx0, __shfl_xor_sync(~0u, mx0, 2));
    mx1 = fmaxf(mx1, __shfl_xor_sync(~0u, mx1, 1));
    mx1 = fmaxf(mx1, __shfl_xor_sync(~0u, mx1, 2));
    float* smax = (float*)(smem + OFF_MAX);
    float* ssum = (float*)(smem + OFF_SUM);
    if ((lane & 3) == 0) { smax[rl0 * 2 + wn] = mx0; smax[rl1 * 2 + wn] = mx1; }
    __syncthreads();   // [A]

    #pragma unroll
    for (int i = 0; i < 8; i++) {
        const int s_ = tid + i * 256;
        const int r = s_ >> 3, sg = s_ & 7;
        const size_t gi = ((size_t)bh * SS + r) * HD + sg * 8;
        const uint32_t so = (r * P2 + sg * 8) * 2;
        cp16(sb + OFF_K_H + so, g_vh + gi);
        cp16(sb + OFF_K_L + so, g_vl + gi);
    }
    CP_COMMIT();

    const float m0 = fmaxf(smax[rl0 * 2], smax[rl0 * 2 + 1]);
    const float m1 = fmaxf(smax[rl1 * 2], smax[rl1 * 2 + 1]);
    float sum0 = 0.f, sum1 = 0.f;
    #pragma unroll
    for (int nt = 0; nt < 16; nt++) {
        acc[nt][0] = __expf(acc[nt][0] - m0);
        acc[nt][1] = __expf(acc[nt][1] - m0);
        acc[nt][2] = __expf(acc[nt][2] - m1);
        acc[nt][3] = __expf(acc[nt][3] - m1);
        sum0 += acc[nt][0] + acc[nt][1];
        sum1 += acc[nt][2] + acc[nt][3];
    }
    sum0 += __shfl_xor_sync(~0u, sum0, 1);
    sum0 += __shfl_xor_sync(~0u, sum0, 2);
    sum1 += __shfl_xor_sync(~0u, sum1, 1);
    sum1 += __shfl_xor_sync(~0u, sum1, 2);
    if ((lane & 3) == 0) { ssum[rl0 * 2 + wn] = sum0; ssum[rl1 * 2 + wn] = sum1; }
    CP_WAIT(0);
    __syncthreads();   // [B]

    const float inv0 = 1.f / (ssum[rl0 * 2] + ssum[rl0 * 2 + 1]);
    const float inv1 = 1.f / (ssum[rl1 * 2] + ssum[rl1 * 2 + 1]);

    uint32_t aPh[8][4], aPl[8][4];
    #pragma unroll
    for (int ks = 0; ks < 8; ks++) {
        const int lo = 2 * ks, hi = 2 * ks + 1;
        split2(acc[lo][0] * inv0, acc[lo][1] * inv0, aPh[ks][0], aPl[ks][0]);
        split2(acc[lo][2] * inv1, acc[lo][3] * inv1, aPh[ks][1], aPl[ks][1]);
        split2(acc[hi][0] * inv0, acc[hi][1] * inv0, aPh[ks][2], aPl[ks][2]);
        split2(acc[hi][2] * inv1, acc[hi][3] * inv1, aPh[ks][3], aPl[ks][3]);
    }

    float ctx[8][4];
    #pragma unroll
    for (int d8 = 0; d8 < 8; d8++)
        #pragma unroll
        for (int c = 0; c < 4; c++) ctx[d8][c] = 0.f;

    const uint32_t vj = lane >> 3, vi = lane & 7;
    #pragma unroll
    for (int ks = 0; ks < 8; ks++) {
        const uint32_t vrow = wn * 128 + ks * 16 + (vj & 1) * 8 + vi;
        const uint32_t vcol = (vj >> 1) * 8;
        uint32_t vb[16];
        #pragma unroll
        for (int g = 0; g < 4; g++)
            ldm_x4_t(&vb[g * 4], sb + OFF_K_H + (vrow * P2 + g * 16 + vcol) * 2);
        #pragma unroll
        for (int d8 = 0; d8 < 8; d8++) mma16816(ctx[d8], aPh[ks], &vb[d8 * 2]);
        #pragma unroll
        for (int d8 = 0; d8 < 8; d8++) mma16816(ctx[d8], aPl[ks], &vb[d8 * 2]);
        #pragma unroll
        for (int g = 0; g < 4; g++)
            ldm_x4_t(&vb[g * 4], sb + OFF_K_L + (vrow * P2 + g * 16 + vcol) * 2);
        #pragma unroll
        for (int d8 = 0; d8 < 8; d8++) mma16816(ctx[d8], aPh[ks], &vb[d8 * 2]);
    }

    float* sctx = (float*)(smem + OFF_CTX);
    if (wn == 1) {
        #pragma unroll
        for (int d8 = 0; d8 < 8; d8++) {
            const int d = d8 * 8 + (lane & 3) * 2;
            *(float2*)&sctx[(wm * 16 + (lane >> 2)) * 66 + d]     = make_float2(ctx[d8][0], ctx[d8][1]);
            *(float2*)&sctx[(wm * 16 + (lane >> 2) + 8) * 66 + d] = make_float2(ctx[d8][2], ctx[d8][3]);
        }
    }
    __syncthreads();   // [C]
    if (wn == 0) {
        #pragma unroll
        for (int d8 = 0; d8 < 8; d8++) {
            const int d = d8 * 8 + (lane & 3) * 2;
            float2 p0 = *(const float2*)&sctx[(wm * 16 + (lane >> 2)) * 66 + d];
            float2 p1 = *(const float2*)&sctx[(wm * 16 + (lane >> 2) + 8) * 66 + d];
            p0.x += ctx[d8][0]; p0.y += ctx[d8][1];
            p1.x += ctx[d8][2]; p1.y += ctx[d8][3];
            const int s0 = qt * 64 + wm * 16 + (lane >> 2);
            *(float2*)&out[(size_t)(b * SS + s0) * HH + h * HD + d]       = p0;
            *(float2*)&out[(size_t)(b * SS + s0 + 8) * HH + h * HD + d]   = p1;
        }
    }
}

// ---------------------------------------------------------------------------
extern "C" void kernel_launch(void* const* d_in, const int* in_sizes, int n_in,
                              void* d_out, int out_size)
{
    const float* X    = (const float*)d_in[0];
    const float* CM   = (const float*)d_in[1];
    const float* MSK  = (const float*)d_in[2];
    const float* Wq   = (const float*)d_in[3];
    const float* bq   = (const float*)d_in[4];
    const float* Wk   = (const float*)d_in[5];
    const float* bk   = (const float*)d_in[6];
    const float* Wv   = (const float*)d_in[7];
    const float* bv   = (const float*)d_in[8];
    const float* wcm  = (const float*)d_in[9];
    const float* bcm  = (const float*)d_in[10];
    float* out = (float*)d_out;

    prep_w<<<dim3(HH / 32, HH / 32, 3), 256>>>(Wq, Wk, Wv);

    cudaFuncSetAttribute(qkv_mma, cudaFuncAttributeMaxDynamicSharedMemorySize, QKV_SMEM);
    qkv_mma<<<dim3(64, 18), 256, QKV_SMEM>>>(X, bq, bk, bv);

    cudaFuncSetAttribute(att_kernel, cudaFuncAttributeMaxDynamicSharedMemorySize, ATT_SMEM);
    att_kernel<<<dim3(4, BH), 256, ATT_SMEM>>>(CM, MSK, wcm, bcm, out);
}